// round 1
// baseline (speedup 1.0000x reference)
#include <cuda_runtime.h>

#define BN 2
#define NN 512
#define TT 24
#define HH 8
#define DD 8
#define EE 64
#define SCALE 0.125f
#define LOG2E 1.44269504088896340736f

// Intermediate per-head attention output (b, n, t, e) before output projection.
__device__ float g_mid[BN * NN * TT * EE];

__device__ __forceinline__ float fast_exp2(float x) {
    float y;
    asm("ex2.approx.f32 %0, %1;" : "=f"(y) : "f"(x));
    return y;
}

// One CTA handles 256 queries of one (b, t, h) group. grid = 384 groups * 2 halves.
__global__ __launch_bounds__(256) void attn_kernel(
    const float* __restrict__ Vg, const float* __restrict__ Kg, const float* __restrict__ Qg,
    const float* __restrict__ Wv, const float* __restrict__ Wk, const float* __restrict__ Wq)
{
    __shared__ float sK[NN * DD];
    __shared__ float sV[NN * DD];
    __shared__ float sWk[DD * DD], sWv[DD * DD], sWq[DD * DD];

    const int tid = threadIdx.x;
    const int gid  = blockIdx.x >> 1;
    const int half = blockIdx.x & 1;
    const int h = gid & (HH - 1);
    const int t = (gid >> 3) % TT;
    const int b = gid / (HH * TT);

    if (tid < DD * DD) {
        sWv[tid] = Wv[tid];
        sWk[tid] = Wk[tid];
        sWq[tid] = Wq[tid];
    }
    __syncthreads();

    const size_t base = ((size_t)b * NN * TT + t) * EE + (size_t)h * DD;
    const int rowstride = TT * EE;  // 1536 floats between nodes

    // ---- Project K and V for all 512 nodes into SMEM (2 rows per thread) ----
    for (int r = tid; r < NN; r += 256) {
        const float4* kp = (const float4*)(Kg + base + (size_t)r * rowstride);
        const float4* vp = (const float4*)(Vg + base + (size_t)r * rowstride);
        float4 ka = kp[0], kb = kp[1];
        float4 va = vp[0], vb = vp[1];
        float kr[8] = {ka.x, ka.y, ka.z, ka.w, kb.x, kb.y, kb.z, kb.w};
        float vr[8] = {va.x, va.y, va.z, va.w, vb.x, vb.y, vb.z, vb.w};
        float ko[8], vo[8];
        #pragma unroll
        for (int i = 0; i < DD; i++) {
            float sk = 0.f, sv = 0.f;
            #pragma unroll
            for (int j = 0; j < DD; j++) {
                sk = fmaf(kr[j], sWk[i * DD + j], sk);
                sv = fmaf(vr[j], sWv[i * DD + j], sv);
            }
            ko[i] = sk; vo[i] = sv;
        }
        *(float4*)(sK + r * DD)     = make_float4(ko[0], ko[1], ko[2], ko[3]);
        *(float4*)(sK + r * DD + 4) = make_float4(ko[4], ko[5], ko[6], ko[7]);
        *(float4*)(sV + r * DD)     = make_float4(vo[0], vo[1], vo[2], vo[3]);
        *(float4*)(sV + r * DD + 4) = make_float4(vo[4], vo[5], vo[6], vo[7]);
    }

    // ---- Project this thread's query, folding softmax scale and log2(e) ----
    const int q = half * 256 + tid;
    float qv[8];
    {
        const float4* qp = (const float4*)(Qg + base + (size_t)q * rowstride);
        float4 qa = qp[0], qb = qp[1];
        float qr[8] = {qa.x, qa.y, qa.z, qa.w, qb.x, qb.y, qb.z, qb.w};
        #pragma unroll
        for (int i = 0; i < DD; i++) {
            float s = 0.f;
            #pragma unroll
            for (int j = 0; j < DD; j++) s = fmaf(qr[j], sWq[i * DD + j], s);
            qv[i] = s * (SCALE * LOG2E);
        }
    }
    __syncthreads();

    // ---- Main loop over all 512 keys; SMEM reads are warp broadcasts ----
    float acc0 = 0.f, acc1 = 0.f, acc2 = 0.f, acc3 = 0.f;
    float acc4 = 0.f, acc5 = 0.f, acc6 = 0.f, acc7 = 0.f;
    float l = 0.f;
    #pragma unroll 4
    for (int k = 0; k < NN; k++) {
        float4 ka = *(const float4*)(sK + k * DD);
        float4 kb = *(const float4*)(sK + k * DD + 4);
        float s = qv[0] * ka.x;
        s = fmaf(qv[1], ka.y, s);
        s = fmaf(qv[2], ka.z, s);
        s = fmaf(qv[3], ka.w, s);
        s = fmaf(qv[4], kb.x, s);
        s = fmaf(qv[5], kb.y, s);
        s = fmaf(qv[6], kb.z, s);
        s = fmaf(qv[7], kb.w, s);
        float p = fast_exp2(s);   // scale*log2e already folded into qv
        l += p;
        float4 va = *(const float4*)(sV + k * DD);
        float4 vb = *(const float4*)(sV + k * DD + 4);
        acc0 = fmaf(p, va.x, acc0);
        acc1 = fmaf(p, va.y, acc1);
        acc2 = fmaf(p, va.z, acc2);
        acc3 = fmaf(p, va.w, acc3);
        acc4 = fmaf(p, vb.x, acc4);
        acc5 = fmaf(p, vb.y, acc5);
        acc6 = fmaf(p, vb.z, acc6);
        acc7 = fmaf(p, vb.w, acc7);
    }

    const float inv = 1.0f / l;
    float* o = g_mid + base + (size_t)q * rowstride;
    ((float4*)o)[0] = make_float4(acc0 * inv, acc1 * inv, acc2 * inv, acc3 * inv);
    ((float4*)o)[1] = make_float4(acc4 * inv, acc5 * inv, acc6 * inv, acc7 * inv);
}

// Output projection: y[r,:] = x[r,:] @ Wo^T + bo, over R = B*N*T = 24576 rows.
// One CTA handles 16 rows (1024 outputs, 4 per thread).
#define RPB 16
#define WSTRIDE 68   // padded row stride for conflict-free float4 LDS

__global__ __launch_bounds__(256) void proj_kernel(
    const float* __restrict__ Wo, const float* __restrict__ bo, float* __restrict__ out)
{
    __shared__ float sW[EE * WSTRIDE];
    __shared__ float sb[EE];
    __shared__ float sx[RPB * EE];

    const int tid = threadIdx.x;
    #pragma unroll
    for (int i = tid; i < EE * EE; i += 256)
        sW[(i >> 6) * WSTRIDE + (i & 63)] = Wo[i];
    if (tid < EE) sb[tid] = bo[tid];

    const size_t rbase = (size_t)blockIdx.x * RPB * EE;
    #pragma unroll
    for (int i = tid; i < RPB * EE; i += 256) sx[i] = g_mid[rbase + i];
    __syncthreads();

    #pragma unroll
    for (int kk = 0; kk < RPB * EE / 256; kk++) {
        const int o = tid + kk * 256;
        const int r = o >> 6;
        const int i = o & 63;
        float s = sb[i];
        const float* xr = sx + r * EE;
        const float* wr = sW + i * WSTRIDE;
        #pragma unroll
        for (int j = 0; j < EE; j += 4) {
            float4 xv = *(const float4*)(xr + j);
            float4 wv = *(const float4*)(wr + j);
            s = fmaf(xv.x, wv.x, s);
            s = fmaf(xv.y, wv.y, s);
            s = fmaf(xv.z, wv.z, s);
            s = fmaf(xv.w, wv.w, s);
        }
        out[rbase + o] = s;
    }
}

extern "C" void kernel_launch(void* const* d_in, const int* in_sizes, int n_in,
                              void* d_out, int out_size)
{
    const float* values = (const float*)d_in[0];
    const float* keys   = (const float*)d_in[1];
    const float* query  = (const float*)d_in[2];
    const float* Wv     = (const float*)d_in[3];
    const float* Wk     = (const float*)d_in[4];
    const float* Wq     = (const float*)d_in[5];
    const float* Wo     = (const float*)d_in[6];
    const float* bo     = (const float*)d_in[7];

    attn_kernel<<<BN * TT * HH * 2, 256>>>(values, keys, query, Wv, Wk, Wq);
    proj_kernel<<<BN * NN * TT / RPB, 256>>>(Wo, bo, (float*)d_out);
}

// round 2
// speedup vs baseline: 1.1229x; 1.1229x over previous
#include <cuda_runtime.h>

#define BN 2
#define NN 512
#define TT 24
#define HH 8
#define DD 8
#define EE 64
#define SCALE 0.125f
#define LOG2E 1.44269504088896340736f

typedef unsigned long long u64;

// Intermediate per-head attention output (b, n, t, e) before output projection.
__device__ float g_mid[BN * NN * TT * EE];

__device__ __forceinline__ float fast_exp2(float x) {
    float y;
    asm("ex2.approx.f32 %0, %1;" : "=f"(y) : "f"(x));
    return y;
}
__device__ __forceinline__ u64 pack2(float a, float b) {
    u64 r; asm("mov.b64 %0, {%1, %2};" : "=l"(r) : "f"(a), "f"(b)); return r;
}
__device__ __forceinline__ void unpack2(u64 v, float& a, float& b) {
    asm("mov.b64 {%0, %1}, %2;" : "=f"(a), "=f"(b) : "l"(v));
}
__device__ __forceinline__ u64 fma2(u64 a, u64 b, u64 c) {
    u64 d; asm("fma.rn.f32x2 %0, %1, %2, %3;" : "=l"(d) : "l"(a), "l"(b), "l"(c)); return d;
}
__device__ __forceinline__ u64 add2(u64 a, u64 b) {
    u64 d; asm("add.rn.f32x2 %0, %1, %2;" : "=l"(d) : "l"(a), "l"(b)); return d;
}
__device__ __forceinline__ u64 mul2(u64 a, u64 b) {
    u64 d; asm("mul.rn.f32x2 %0, %1, %2;" : "=l"(d) : "l"(a), "l"(b)); return d;
}

// One CTA handles 256 queries of one (b, t, h) group. grid = 384 groups * 2 halves.
__global__ __launch_bounds__(256) void attn_kernel(
    const float* __restrict__ Vg, const float* __restrict__ Kg, const float* __restrict__ Qg,
    const float* __restrict__ Wv, const float* __restrict__ Wk, const float* __restrict__ Wq)
{
    __shared__ float sKT[DD * NN];   // transposed: sKT[j*NN + k]
    __shared__ float sV[NN * DD];    // row-major:  sV[k*DD + j]
    __shared__ float sWk[DD * DD], sWv[DD * DD], sWq[DD * DD];

    const int tid = threadIdx.x;
    const int gid  = blockIdx.x >> 1;
    const int half = blockIdx.x & 1;
    const int h = gid & (HH - 1);
    const int t = (gid >> 3) % TT;
    const int b = gid / (HH * TT);

    if (tid < DD * DD) {
        sWv[tid] = Wv[tid];
        sWk[tid] = Wk[tid];
        sWq[tid] = Wq[tid];
    }
    __syncthreads();

    const size_t base = ((size_t)b * NN * TT + t) * EE + (size_t)h * DD;
    const int rowstride = TT * EE;  // 1536 floats between nodes

    // ---- Project K (transposed) and V (row-major) for all 512 nodes ----
    for (int r = tid; r < NN; r += 256) {
        const float4* kp = (const float4*)(Kg + base + (size_t)r * rowstride);
        const float4* vp = (const float4*)(Vg + base + (size_t)r * rowstride);
        float4 ka = kp[0], kb = kp[1];
        float4 va = vp[0], vb = vp[1];
        float kr[8] = {ka.x, ka.y, ka.z, ka.w, kb.x, kb.y, kb.z, kb.w};
        float vr[8] = {va.x, va.y, va.z, va.w, vb.x, vb.y, vb.z, vb.w};
        float vo[8];
        #pragma unroll
        for (int i = 0; i < DD; i++) {
            float sk = 0.f, sv = 0.f;
            #pragma unroll
            for (int j = 0; j < DD; j++) {
                sk = fmaf(kr[j], sWk[i * DD + j], sk);
                sv = fmaf(vr[j], sWv[i * DD + j], sv);
            }
            sKT[i * NN + r] = sk;     // consecutive lanes -> consecutive banks
            vo[i] = sv;
        }
        *(float4*)(sV + r * DD)     = make_float4(vo[0], vo[1], vo[2], vo[3]);
        *(float4*)(sV + r * DD + 4) = make_float4(vo[4], vo[5], vo[6], vo[7]);
    }

    // ---- Project this thread's query, fold scale*log2e, pack as (q,q) pairs ----
    const int q = half * 256 + tid;
    u64 qp[8];
    {
        const float4* qptr = (const float4*)(Qg + base + (size_t)q * rowstride);
        float4 qa = qptr[0], qb = qptr[1];
        float qr[8] = {qa.x, qa.y, qa.z, qa.w, qb.x, qb.y, qb.z, qb.w};
        #pragma unroll
        for (int i = 0; i < DD; i++) {
            float s = 0.f;
            #pragma unroll
            for (int j = 0; j < DD; j++) s = fmaf(qr[j], sWq[i * DD + j], s);
            s *= (SCALE * LOG2E);
            qp[i] = pack2(s, s);
        }
    }
    __syncthreads();

    // ---- Main loop: 4 keys per iteration, packed f32x2 throughout.
    //      All SMEM reads are warp broadcasts (every lane reads same address).
    u64 acc01 = 0, acc23 = 0, acc45 = 0, acc67 = 0;  // bit pattern 0 == (0.f, 0.f)
    u64 lp = 0;
    #pragma unroll 2
    for (int k = 0; k < NN; k += 4) {
        u64 s01 = 0, s23 = 0;
        #pragma unroll
        for (int j = 0; j < DD; j++) {
            ulonglong2 kv = *(const ulonglong2*)(sKT + j * NN + k);  // 4 keys at dim j
            s01 = fma2(kv.x, qp[j], s01);
            s23 = fma2(kv.y, qp[j], s23);
        }
        float s0, s1, s2, s3;
        unpack2(s01, s0, s1);
        unpack2(s23, s2, s3);
        float p0 = fast_exp2(s0), p1 = fast_exp2(s1);
        float p2 = fast_exp2(s2), p3 = fast_exp2(s3);
        lp = add2(lp, pack2(p0, p1));
        lp = add2(lp, pack2(p2, p3));

        const float pv[4] = {p0, p1, p2, p3};
        #pragma unroll
        for (int kk = 0; kk < 4; kk++) {
            const ulonglong2* vp = (const ulonglong2*)(sV + (k + kk) * DD);
            ulonglong2 va = vp[0];   // (v0,v1),(v2,v3)
            ulonglong2 vb = vp[1];   // (v4,v5),(v6,v7)
            u64 pp = pack2(pv[kk], pv[kk]);
            acc01 = fma2(pp, va.x, acc01);
            acc23 = fma2(pp, va.y, acc23);
            acc45 = fma2(pp, vb.x, acc45);
            acc67 = fma2(pp, vb.y, acc67);
        }
    }

    float l0, l1;
    unpack2(lp, l0, l1);
    const float inv = 1.0f / (l0 + l1);
    const u64 invp = pack2(inv, inv);

    ulonglong2 oa, ob;
    oa.x = mul2(acc01, invp); oa.y = mul2(acc23, invp);
    ob.x = mul2(acc45, invp); ob.y = mul2(acc67, invp);
    float* o = g_mid + base + (size_t)q * rowstride;
    ((ulonglong2*)o)[0] = oa;
    ((ulonglong2*)o)[1] = ob;
}

// Output projection: y[r,:] = x[r,:] @ Wo^T + bo, over R = B*N*T = 24576 rows.
// 256 threads, 32 rows per CTA. lane = row (conflict-free via stride-65 pad),
// warp owns 8 output columns (all W reads are broadcasts). Packed f32x2 dots.
#define RPB 32
#define XS 65      // padded x row stride
#define WS 68      // padded W^T row stride (16B-aligned at i0 multiples of 8)

__global__ __launch_bounds__(256) void proj_kernel(
    const float* __restrict__ Wo, const float* __restrict__ bo, float* __restrict__ out)
{
    __shared__ float sWT[EE * WS];   // sWT[j*WS + i] = Wo[i*EE + j]
    __shared__ float sb[EE];
    __shared__ float sx[RPB * XS];

    const int tid = threadIdx.x;
    for (int idx = tid; idx < EE * EE; idx += 256) {
        int i = idx >> 6, j = idx & 63;
        sWT[j * WS + i] = Wo[idx];
    }
    if (tid < EE) sb[tid] = bo[tid];

    const size_t rbase = (size_t)blockIdx.x * RPB * EE;
    for (int idx = tid; idx < RPB * EE; idx += 256)
        sx[(idx >> 6) * XS + (idx & 63)] = g_mid[rbase + idx];
    __syncthreads();

    const int w = tid >> 5;       // warp -> output column group
    const int lane = tid & 31;    // lane -> row
    const int i0 = w * 8;

    u64 a01 = pack2(sb[i0 + 0], sb[i0 + 1]);
    u64 a23 = pack2(sb[i0 + 2], sb[i0 + 3]);
    u64 a45 = pack2(sb[i0 + 4], sb[i0 + 5]);
    u64 a67 = pack2(sb[i0 + 6], sb[i0 + 7]);

    const float* xr = sx + lane * XS;
    #pragma unroll 8
    for (int j = 0; j < EE; j++) {
        float xj = xr[j];                          // conflict-free (stride 65)
        u64 xp = pack2(xj, xj);
        const ulonglong2* wp = (const ulonglong2*)(sWT + j * WS + i0);  // broadcast
        ulonglong2 wa = wp[0];
        ulonglong2 wb = wp[1];
        a01 = fma2(xp, wa.x, a01);
        a23 = fma2(xp, wa.y, a23);
        a45 = fma2(xp, wb.x, a45);
        a67 = fma2(xp, wb.y, a67);
    }

    float* orow = out + rbase + (size_t)lane * EE + i0;
    ulonglong2 oa; oa.x = a01; oa.y = a23;
    ulonglong2 ob; ob.x = a45; ob.y = a67;
    ((ulonglong2*)orow)[0] = oa;
    ((ulonglong2*)orow)[1] = ob;
}

extern "C" void kernel_launch(void* const* d_in, const int* in_sizes, int n_in,
                              void* d_out, int out_size)
{
    const float* values = (const float*)d_in[0];
    const float* keys   = (const float*)d_in[1];
    const float* query  = (const float*)d_in[2];
    const float* Wv     = (const float*)d_in[3];
    const float* Wk     = (const float*)d_in[4];
    const float* Wq     = (const float*)d_in[5];
    const float* Wo     = (const float*)d_in[6];
    const float* bo     = (const float*)d_in[7];

    attn_kernel<<<BN * TT * HH * 2, 256>>>(values, keys, query, Wv, Wk, Wq);
    proj_kernel<<<BN * NN * TT / RPB, 256>>>(Wo, bo, (float*)d_out);
}

// round 3
// speedup vs baseline: 1.3971x; 1.2442x over previous
#include <cuda_runtime.h>

#define BN 2
#define NN 512
#define TT 24
#define HH 8
#define DD 8
#define EE 64
#define SCALE 0.125f
#define LOG2E 1.44269504088896340736f

typedef unsigned long long u64;

// Intermediate per-head attention output (b, n, t, e) before output projection.
__device__ float g_mid[BN * NN * TT * EE];

__device__ __forceinline__ float fast_exp2(float x) {
    float y;
    asm("ex2.approx.f32 %0, %1;" : "=f"(y) : "f"(x));
    return y;
}
__device__ __forceinline__ u64 pack2(float a, float b) {
    u64 r; asm("mov.b64 %0, {%1, %2};" : "=l"(r) : "f"(a), "f"(b)); return r;
}
__device__ __forceinline__ void unpack2(u64 v, float& a, float& b) {
    asm("mov.b64 {%0, %1}, %2;" : "=f"(a), "=f"(b) : "l"(v));
}
__device__ __forceinline__ u64 fma2(u64 a, u64 b, u64 c) {
    u64 d; asm("fma.rn.f32x2 %0, %1, %2, %3;" : "=l"(d) : "l"(a), "l"(b), "l"(c)); return d;
}
__device__ __forceinline__ u64 add2(u64 a, u64 b) {
    u64 d; asm("add.rn.f32x2 %0, %1, %2;" : "=l"(d) : "l"(a), "l"(b)); return d;
}
__device__ __forceinline__ u64 mul2(u64 a, u64 b) {
    u64 d; asm("mul.rn.f32x2 %0, %1, %2;" : "=l"(d) : "l"(a), "l"(b)); return d;
}

// One CTA per (b, t, h) group: 256 threads, 2 queries per thread. grid = 384.
__global__ __launch_bounds__(256, 2) void attn_kernel(
    const float* __restrict__ Vg, const float* __restrict__ Kg, const float* __restrict__ Qg,
    const float* __restrict__ Wv, const float* __restrict__ Wk, const float* __restrict__ Wq)
{
    __shared__ float sKT[DD * NN];   // sKT[j*NN + k]
    __shared__ float sVT[DD * NN];   // sVT[j*NN + k]
    __shared__ float sWk[DD * DD], sWv[DD * DD], sWq[DD * DD];

    const int tid = threadIdx.x;
    const int gid = blockIdx.x;
    const int h = gid & (HH - 1);
    const int t = (gid >> 3) % TT;
    const int b = gid / (HH * TT);

    if (tid < DD * DD) {
        sWv[tid] = Wv[tid];
        sWk[tid] = Wk[tid];
        sWq[tid] = Wq[tid];
    }
    __syncthreads();

    const size_t base = ((size_t)b * NN * TT + t) * EE + (size_t)h * DD;
    const int rowstride = TT * EE;  // 1536 floats between nodes

    // ---- Project K and V (both transposed) for all 512 nodes ----
    for (int r = tid; r < NN; r += 256) {
        const float4* kp = (const float4*)(Kg + base + (size_t)r * rowstride);
        const float4* vp = (const float4*)(Vg + base + (size_t)r * rowstride);
        float4 ka = kp[0], kb = kp[1];
        float4 va = vp[0], vb = vp[1];
        float kr[8] = {ka.x, ka.y, ka.z, ka.w, kb.x, kb.y, kb.z, kb.w};
        float vr[8] = {va.x, va.y, va.z, va.w, vb.x, vb.y, vb.z, vb.w};
        #pragma unroll
        for (int i = 0; i < DD; i++) {
            float sk = 0.f, sv = 0.f;
            #pragma unroll
            for (int j = 0; j < DD; j++) {
                sk = fmaf(kr[j], sWk[i * DD + j], sk);
                sv = fmaf(vr[j], sWv[i * DD + j], sv);
            }
            sKT[i * NN + r] = sk;    // consecutive lanes -> consecutive banks
            sVT[i * NN + r] = sv;
        }
    }

    // ---- Project both queries of this thread; fold scale*log2e; pack dup ----
    u64 qpA[8], qpB[8];
    #pragma unroll
    for (int sel = 0; sel < 2; sel++) {
        const int q = tid + sel * 256;
        const float4* qptr = (const float4*)(Qg + base + (size_t)q * rowstride);
        float4 qa = qptr[0], qb = qptr[1];
        float qr[8] = {qa.x, qa.y, qa.z, qa.w, qb.x, qb.y, qb.z, qb.w};
        #pragma unroll
        for (int i = 0; i < DD; i++) {
            float s = 0.f;
            #pragma unroll
            for (int j = 0; j < DD; j++) s = fmaf(qr[j], sWq[i * DD + j], s);
            s *= (SCALE * LOG2E);
            if (sel == 0) qpA[i] = pack2(s, s); else qpB[i] = pack2(s, s);
        }
    }
    __syncthreads();

    // ---- Main loop: 4 keys / iter, 2 queries / thread, packed f32x2.
    //      All SMEM reads are LDS.128 warp broadcasts shared by both queries.
    u64 accA[8], accB[8];
    #pragma unroll
    for (int j = 0; j < 8; j++) { accA[j] = 0; accB[j] = 0; }
    u64 lpA = 0, lpB = 0;

    #pragma unroll 2
    for (int k = 0; k < NN; k += 4) {
        u64 sA01 = 0, sA23 = 0, sB01 = 0, sB23 = 0;
        #pragma unroll
        for (int j = 0; j < DD; j++) {
            ulonglong2 kv = *(const ulonglong2*)(sKT + j * NN + k);  // 4 keys @ dim j
            sA01 = fma2(kv.x, qpA[j], sA01);
            sA23 = fma2(kv.y, qpA[j], sA23);
            sB01 = fma2(kv.x, qpB[j], sB01);
            sB23 = fma2(kv.y, qpB[j], sB23);
        }
        float a0, a1, a2, a3, b0, b1, b2, b3;
        unpack2(sA01, a0, a1); unpack2(sA23, a2, a3);
        unpack2(sB01, b0, b1); unpack2(sB23, b2, b3);
        u64 pA01 = pack2(fast_exp2(a0), fast_exp2(a1));
        u64 pA23 = pack2(fast_exp2(a2), fast_exp2(a3));
        u64 pB01 = pack2(fast_exp2(b0), fast_exp2(b1));
        u64 pB23 = pack2(fast_exp2(b2), fast_exp2(b3));
        lpA = add2(lpA, pA01); lpA = add2(lpA, pA23);
        lpB = add2(lpB, pB01); lpB = add2(lpB, pB23);

        #pragma unroll
        for (int j = 0; j < DD; j++) {
            ulonglong2 vv = *(const ulonglong2*)(sVT + j * NN + k);  // 4 keys @ dim j
            accA[j] = fma2(pA01, vv.x, accA[j]);
            accA[j] = fma2(pA23, vv.y, accA[j]);
            accB[j] = fma2(pB01, vv.x, accB[j]);
            accB[j] = fma2(pB23, vv.y, accB[j]);
        }
    }

    // ---- Epilogue: fold packed halves, normalize, store both query rows ----
    #pragma unroll
    for (int sel = 0; sel < 2; sel++) {
        const u64* acc = sel ? accB : accA;
        u64 lp = sel ? lpB : lpA;
        float l0, l1;
        unpack2(lp, l0, l1);
        const float inv = 1.0f / (l0 + l1);
        float o[8];
        #pragma unroll
        for (int j = 0; j < 8; j++) {
            float x, y;
            unpack2(acc[j], x, y);
            o[j] = (x + y) * inv;
        }
        float* op = g_mid + base + (size_t)(tid + sel * 256) * rowstride;
        ((float4*)op)[0] = make_float4(o[0], o[1], o[2], o[3]);
        ((float4*)op)[1] = make_float4(o[4], o[5], o[6], o[7]);
    }
}

// Output projection: y[r,:] = x[r,:] @ Wo^T + bo, R = B*N*T = 24576 rows.
// 256 threads, 64 rows/CTA (grid 384). warp -> 8 output cols (W reads broadcast);
// lane -> 2 rows (lane, lane+32). x loaded 4-at-a-time via LDS.128 (2-way floor).
#define RPB 64
#define XS 68      // padded x row stride (16B-aligned quads, 2-way = crossbar floor)
#define WS 68      // padded W^T row stride

__global__ __launch_bounds__(256) void proj_kernel(
    const float* __restrict__ Wo, const float* __restrict__ bo, float* __restrict__ out)
{
    __shared__ float sWT[EE * WS];   // sWT[j*WS + i] = Wo[i*EE + j]
    __shared__ float sb[EE];
    __shared__ float sx[RPB * XS];

    const int tid = threadIdx.x;
    for (int idx = tid; idx < EE * EE; idx += 256) {
        int i = idx >> 6, j = idx & 63;
        sWT[j * WS + i] = Wo[idx];
    }
    if (tid < EE) sb[tid] = bo[tid];

    const size_t rbase = (size_t)blockIdx.x * RPB * EE;
    for (int idx = tid; idx < RPB * EE; idx += 256)
        sx[(idx >> 6) * XS + (idx & 63)] = g_mid[rbase + idx];
    __syncthreads();

    const int w = tid >> 5;       // warp -> output column group
    const int lane = tid & 31;    // lane -> rows lane, lane+32
    const int i0 = w * 8;

    u64 a01 = pack2(sb[i0 + 0], sb[i0 + 1]);
    u64 a23 = pack2(sb[i0 + 2], sb[i0 + 3]);
    u64 a45 = pack2(sb[i0 + 4], sb[i0 + 5]);
    u64 a67 = pack2(sb[i0 + 6], sb[i0 + 7]);
    u64 c01 = a01, c23 = a23, c45 = a45, c67 = a67;

    const float* xrA = sx + lane * XS;
    const float* xrB = sx + (lane + 32) * XS;
    #pragma unroll
    for (int j = 0; j < EE; j += 4) {
        float4 xa = *(const float4*)(xrA + j);   // 2-way (crossbar floor)
        float4 xb = *(const float4*)(xrB + j);
        const float xva[4] = {xa.x, xa.y, xa.z, xa.w};
        const float xvb[4] = {xb.x, xb.y, xb.z, xb.w};
        #pragma unroll
        for (int jj = 0; jj < 4; jj++) {
            const ulonglong2* wp = (const ulonglong2*)(sWT + (j + jj) * WS + i0);  // broadcast
            ulonglong2 wa = wp[0];
            ulonglong2 wb = wp[1];
            u64 xpa = pack2(xva[jj], xva[jj]);
            u64 xpb = pack2(xvb[jj], xvb[jj]);
            a01 = fma2(xpa, wa.x, a01);
            a23 = fma2(xpa, wa.y, a23);
            a45 = fma2(xpa, wb.x, a45);
            a67 = fma2(xpa, wb.y, a67);
            c01 = fma2(xpb, wa.x, c01);
            c23 = fma2(xpb, wa.y, c23);
            c45 = fma2(xpb, wb.x, c45);
            c67 = fma2(xpb, wb.y, c67);
        }
    }

    float* orowA = out + rbase + (size_t)lane * EE + i0;
    float* orowB = out + rbase + (size_t)(lane + 32) * EE + i0;
    ulonglong2 oa; oa.x = a01; oa.y = a23;
    ulonglong2 ob; ob.x = a45; ob.y = a67;
    ulonglong2 oc; oc.x = c01; oc.y = c23;
    ulonglong2 od; od.x = c45; od.y = c67;
    ((ulonglong2*)orowA)[0] = oa;
    ((ulonglong2*)orowA)[1] = ob;
    ((ulonglong2*)orowB)[0] = oc;
    ((ulonglong2*)orowB)[1] = od;
}

extern "C" void kernel_launch(void* const* d_in, const int* in_sizes, int n_in,
                              void* d_out, int out_size)
{
    const float* values = (const float*)d_in[0];
    const float* keys   = (const float*)d_in[1];
    const float* query  = (const float*)d_in[2];
    const float* Wv     = (const float*)d_in[3];
    const float* Wk     = (const float*)d_in[4];
    const float* Wq     = (const float*)d_in[5];
    const float* Wo     = (const float*)d_in[6];
    const float* bo     = (const float*)d_in[7];

    attn_kernel<<<BN * TT * HH, 256>>>(values, keys, query, Wv, Wk, Wq);
    proj_kernel<<<BN * NN * TT / RPB, 256>>>(Wo, bo, (float*)d_out);
}